// round 16
// baseline (speedup 1.0000x reference)
#include <cuda_runtime.h>
#include <cuda_fp16.h>
#include <cstdint>
#include <cstddef>

#define NN 100000
#define EE 1600000
#define TT (EE + NN)

// ---------------- scratch (static device globals; no allocation) ----------------
__device__ float    g_h[(size_t)NN * 96];    // h fp32 (agg gather payload)
__device__ float    g_out[(size_t)NN * 96];  // agg output (fp32, flat thirds)
__device__ unsigned g_x16[(size_t)NN * 64];  // x fp16 (gemm1 A)
__device__ unsigned g_s16[(size_t)NN * 16];  // thirds out fp16 (gemm2 A)
__device__ unsigned g_w16a[6144];            // W1 fp16
__device__ unsigned g_w16b[1536];            // W2 fp16
__device__ float    g_es[NN];
__device__ float    g_ed[NN];
__device__ int      g_deg[NN];
__device__ int      g_rowptr[NN + 1];
__device__ int      g_cursor[NN];
__device__ int      g_csr[TT];
__device__ int      g_bsum[1024];
__device__ int      g_is64;

// ---------------- f32x2 / cp.async / mma helpers ----------------
__device__ __forceinline__ unsigned long long pack_dup(float a) {
    unsigned long long r;
    unsigned ai = __float_as_uint(a);
    asm("mov.b64 %0, {%1, %1};" : "=l"(r) : "r"(ai));
    return r;
}
__device__ __forceinline__ unsigned long long pack_f2(float a, float b) {
    unsigned long long r;
    asm("mov.b64 %0, {%1, %2};" : "=l"(r) : "f"(a), "f"(b));
    return r;
}
__device__ __forceinline__ float2 unpack_f2(unsigned long long u) {
    float2 f;
    asm("mov.b64 {%0, %1}, %2;" : "=f"(f.x), "=f"(f.y) : "l"(u));
    return f;
}
__device__ __forceinline__ void fma2(unsigned long long& d, unsigned long long a,
                                     unsigned long long b) {
    asm("fma.rn.f32x2 %0, %1, %2, %0;" : "+l"(d) : "l"(a), "l"(b));
}
__device__ __forceinline__ void cp16(void* smem_dst, const void* gsrc, int valid_bytes) {
    unsigned sm = (unsigned)__cvta_generic_to_shared(smem_dst);
    asm volatile("cp.async.cg.shared.global [%0], [%1], 16, %2;"
                 :: "r"(sm), "l"(gsrc), "r"(valid_bytes));
}
__device__ __forceinline__ void cp_commit() {
    asm volatile("cp.async.commit_group;" ::: "memory");
}
__device__ __forceinline__ void cp_wait0() {
    asm volatile("cp.async.wait_group 0;" ::: "memory");
}
__device__ __forceinline__ void ldsm4(unsigned* r, unsigned addr) {
    asm volatile("ldmatrix.sync.aligned.m8n8.x4.shared.b16 {%0,%1,%2,%3}, [%4];"
                 : "=r"(r[0]), "=r"(r[1]), "=r"(r[2]), "=r"(r[3]) : "r"(addr));
}
__device__ __forceinline__ void ldsm4t(unsigned* r, unsigned addr) {
    asm volatile("ldmatrix.sync.aligned.m8n8.x4.trans.shared.b16 {%0,%1,%2,%3}, [%4];"
                 : "=r"(r[0]), "=r"(r[1]), "=r"(r[2]), "=r"(r[3]) : "r"(addr));
}
__device__ __forceinline__ void mma16816(float* d, const unsigned* a, const unsigned* b) {
    asm volatile(
        "mma.sync.aligned.m16n8k16.row.col.f32.f16.f16.f32 "
        "{%0,%1,%2,%3}, {%4,%5,%6,%7}, {%8,%9}, {%0,%1,%2,%3};"
        : "+f"(d[0]), "+f"(d[1]), "+f"(d[2]), "+f"(d[3])
        : "r"(a[0]), "r"(a[1]), "r"(a[2]), "r"(a[3]), "r"(b[0]), "r"(b[1]));
}
__device__ __forceinline__ unsigned pack_h2(float a, float b) {
    __half2 h = __floats2half2_rn(a, b);
    return *reinterpret_cast<unsigned*>(&h);
}

// ---------------- edge-index dtype probe ----------------
__global__ void k_probe(const int* __restrict__ ei32) {
    if (threadIdx.x == 0 && blockIdx.x == 0) {
        int acc = 0;
        #pragma unroll 8
        for (int i = 1; i < 512; i += 2) acc |= ei32[i];
        g_is64 = (acc == 0) ? 1 : 0;
    }
}

__device__ __forceinline__ int load_idx(const void* ei, size_t i, int is64, int N) {
    int v = is64 ? (int)((const long long*)ei)[i] : ((const int*)ei)[i];
    v = v < 0 ? 0 : v;
    return v >= N ? N - 1 : v;
}

// ---------------- fp16 converts ----------------
__global__ void k_cvt_w(const float2* __restrict__ W1, const float2* __restrict__ W2) {
    int i = blockIdx.x * blockDim.x + threadIdx.x;
    if (i < 6144) {
        float2 f = __ldg(W1 + i);
        g_w16a[i] = pack_h2(f.x, f.y);
    } else if (i < 7680) {
        float2 f = __ldg(W2 + (i - 6144));
        g_w16b[i - 6144] = pack_h2(f.x, f.y);
    }
}

__global__ void k_cvt_x(const float4* __restrict__ x4, int n) {
    int i = blockIdx.x * blockDim.x + threadIdx.x;
    if (i >= n) return;
    float4 v = __ldg(x4 + i);
    uint2 u;
    u.x = pack_h2(v.x, v.y);
    u.y = pack_h2(v.z, v.w);
    reinterpret_cast<uint2*>(g_x16)[i] = u;
}

// ---------------- CSR construction ----------------
__global__ void k_init_deg(int N) {
    int i = blockIdx.x * blockDim.x + threadIdx.x;
    if (i < N) g_deg[i] = 1;  // self-loop
}

__global__ void k_count(const void* __restrict__ ei, int E, int N) {
    int i = blockIdx.x * blockDim.x + threadIdx.x;
    if (i < E) {
        int d = load_idx(ei, (size_t)E + i, g_is64, N);
        atomicAdd(&g_deg[d], 1);
    }
}

__global__ void k_scan_blocks(int N) {
    __shared__ int ws[32];
    int i = blockIdx.x * 1024 + threadIdx.x;
    int v = (i < N) ? g_deg[i] : 0;
    int x = v;
    int lane = threadIdx.x & 31, wid = threadIdx.x >> 5;
    #pragma unroll
    for (int o = 1; o < 32; o <<= 1) {
        int y = __shfl_up_sync(0xffffffffu, x, o);
        if (lane >= o) x += y;
    }
    if (lane == 31) ws[wid] = x;
    __syncthreads();
    if (wid == 0) {
        int w = ws[lane];
        #pragma unroll
        for (int o = 1; o < 32; o <<= 1) {
            int y = __shfl_up_sync(0xffffffffu, w, o);
            if (lane >= o) w += y;
        }
        ws[lane] = w;
    }
    __syncthreads();
    int excl = x - v + (wid ? ws[wid - 1] : 0);
    if (i < N) g_rowptr[i] = excl;
    if (threadIdx.x == 1023) g_bsum[blockIdx.x] = ws[31];
}

__global__ void k_scan_sums(int G, int N) {
    __shared__ int ws[32];
    int tid = threadIdx.x;
    int v = (tid < G) ? g_bsum[tid] : 0;
    int x = v;
    int lane = tid & 31, wid = tid >> 5;
    #pragma unroll
    for (int o = 1; o < 32; o <<= 1) {
        int y = __shfl_up_sync(0xffffffffu, x, o);
        if (lane >= o) x += y;
    }
    if (lane == 31) ws[wid] = x;
    __syncthreads();
    if (wid == 0) {
        int w = ws[lane];
        #pragma unroll
        for (int o = 1; o < 32; o <<= 1) {
            int y = __shfl_up_sync(0xffffffffu, w, o);
            if (lane >= o) w += y;
        }
        ws[lane] = w;
    }
    __syncthreads();
    int excl = x - v + (wid ? ws[wid - 1] : 0);
    if (tid < G) g_bsum[tid] = excl;
    if (tid == 1023) g_rowptr[N] = ws[31];
}

__global__ void k_scan_add(int N) {
    int i = blockIdx.x * blockDim.x + threadIdx.x;
    if (i < N) {
        int v = g_rowptr[i] + g_bsum[i >> 10];
        g_rowptr[i] = v;
        g_cursor[i] = v;
    }
}

__global__ void k_fill(const void* __restrict__ ei, int E, int N) {
    int i = blockIdx.x * blockDim.x + threadIdx.x;
    int tot = E + N;
    if (i >= tot) return;
    int s, d;
    if (i < E) {
        int is64 = g_is64;
        s = load_idx(ei, i, is64, N);
        d = load_idx(ei, (size_t)E + i, is64, N);
    } else {
        s = i - E;
        d = s;
    }
    int pos = atomicAdd(&g_cursor[d], 1);
    if (pos < TT) g_csr[pos] = s;
}

// ---------------- tensor-core GEMM + fused scores (fp32 h out) ---------------------
template <int K>
__global__ __launch_bounds__(256, 2)
void k_gemm16(const __half* __restrict__ A16, const __half* __restrict__ W16,
              float* __restrict__ C, const float* __restrict__ a_s,
              const float* __restrict__ a_d, float* __restrict__ es,
              float* __restrict__ ed, int N) {
    constexpr int BK = (K >= 64) ? 64 : K;
    constexpr int NCH = K / BK;
    constexpr int ACH = BK / 8;
    __shared__ __align__(16) __half As[128][BK + 8];
    __shared__ __align__(16) __half Ws[BK][104];
    __shared__ float sdot[128];
    __shared__ float ddot[128];
    int tid = threadIdx.x;
    int lane = tid & 31, wid = tid >> 5;
    int row0 = blockIdx.x * 128;
    int wr = (wid & 3) * 32;
    int wc = (wid >> 2) * 48;

    for (int i = tid; i < 128; i += 256) {
        sdot[i] = 0.f;
        ddot[i] = 0.f;
    }

    float d[2][6][4];
    #pragma unroll
    for (int mi = 0; mi < 2; ++mi)
        #pragma unroll
        for (int nj = 0; nj < 6; ++nj)
            #pragma unroll
            for (int q = 0; q < 4; ++q) d[mi][nj][q] = 0.f;

    for (int ch = 0; ch < NCH; ++ch) {
        for (int i = tid; i < 128 * ACH; i += 256) {
            int r = i / ACH, c = i % ACH;
            bool ok = (row0 + r) < N;
            const __half* src = A16 + (ok ? ((size_t)(row0 + r) * K + ch * BK + c * 8) : 0);
            cp16(&As[r][c * 8], src, ok ? 16 : 0);
        }
        for (int i = tid; i < BK * 12; i += 256) {
            int k = i / 12, c = i % 12;
            cp16(&Ws[k][c * 8], W16 + (size_t)(ch * BK + k) * 96 + c * 8, 16);
        }
        cp_commit();
        cp_wait0();
        __syncthreads();

        #pragma unroll
        for (int k0 = 0; k0 < BK; k0 += 16) {
            unsigned a[2][4], b[3][4];
            #pragma unroll
            for (int mi = 0; mi < 2; ++mi)
                ldsm4(a[mi], (unsigned)__cvta_generic_to_shared(
                                 &As[wr + mi * 16 + (lane & 15)][k0 + (lane >> 4) * 8]));
            #pragma unroll
            for (int nj = 0; nj < 3; ++nj)
                ldsm4t(b[nj], (unsigned)__cvta_generic_to_shared(
                                  &Ws[k0 + (lane & 15)][wc + nj * 16 + (lane >> 4) * 8]));
            #pragma unroll
            for (int mi = 0; mi < 2; ++mi)
                #pragma unroll
                for (int nj = 0; nj < 6; ++nj)
                    mma16816(d[mi][nj], a[mi], &b[nj >> 1][(nj & 1) * 2]);
        }
        __syncthreads();
    }

    int groupID = lane >> 2;
    int c0 = (lane & 3) * 2;
    float sa[2][2] = {{0.f, 0.f}, {0.f, 0.f}};
    float da[2][2] = {{0.f, 0.f}, {0.f, 0.f}};
    #pragma unroll
    for (int mi = 0; mi < 2; ++mi) {
        int r1 = row0 + wr + mi * 16 + groupID;
        int r2 = r1 + 8;
        #pragma unroll
        for (int nj = 0; nj < 6; ++nj) {
            int col = wc + nj * 8 + c0;
            float as0 = __ldg(&a_s[col]), as1 = __ldg(&a_s[col + 1]);
            float ad0 = __ldg(&a_d[col]), ad1 = __ldg(&a_d[col + 1]);
            sa[mi][0] += d[mi][nj][0] * as0 + d[mi][nj][1] * as1;
            da[mi][0] += d[mi][nj][0] * ad0 + d[mi][nj][1] * ad1;
            sa[mi][1] += d[mi][nj][2] * as0 + d[mi][nj][3] * as1;
            da[mi][1] += d[mi][nj][2] * ad0 + d[mi][nj][3] * ad1;
            if (r1 < N)
                *reinterpret_cast<float2*>(&C[(size_t)r1 * 96 + col]) =
                    make_float2(d[mi][nj][0], d[mi][nj][1]);
            if (r2 < N)
                *reinterpret_cast<float2*>(&C[(size_t)r2 * 96 + col]) =
                    make_float2(d[mi][nj][2], d[mi][nj][3]);
        }
        int lr1 = wr + mi * 16 + groupID;
        atomicAdd(&sdot[lr1], sa[mi][0]);
        atomicAdd(&ddot[lr1], da[mi][0]);
        atomicAdd(&sdot[lr1 + 8], sa[mi][1]);
        atomicAdd(&ddot[lr1 + 8], da[mi][1]);
    }
    __syncthreads();
    for (int i = tid; i < 128; i += 256) {
        int r = row0 + i;
        if (r < N) {
            es[r] = sdot[i];
            ed[r] = ddot[i];
        }
    }
}

// ---------------- warp-per-node softmax aggregation ---------------------------------
// fp32 float4 gather (no cvt instrs); (p,s) staged in smem (1 LDS.64 vs 2 SHFL);
// f32x2 packed FMAs; A/B accumulator sets for ILP. No max pass (shift-invariance).
__global__ void k_agg(const float4* __restrict__ h4, const float* __restrict__ bias,
                      float* __restrict__ outp, int N) {
    __shared__ int2 ps[8][32];  // per-warp staging: (.x = p bits, .y = s)
    int gw = (blockIdx.x * blockDim.x + threadIdx.x) >> 5;
    if (gw >= N) return;
    int lane = threadIdx.x & 31;
    int wib = (threadIdx.x >> 5) & 7;
    int beg = g_rowptr[gw], end = g_rowptr[gw + 1];
    float edn = g_ed[gw];

    unsigned long long accA0 = 0ull, accA1 = 0ull, accB0 = 0ull, accB1 = 0ull;
    float psum = 0.f;

    for (int j0 = beg; j0 < end; j0 += 32) {
        int j = j0 + lane;
        int s = 0;
        float p = 0.f;
        if (j < end) {
            s = __ldg(&g_csr[j]);
            float e = __ldg(&g_es[s]) + edn;
            e = fmaxf(e, 0.2f * e);
            p = __expf(e);
        }
        psum += p;
        ps[wib][lane] = make_int2(__float_as_int(p), s);
        __syncwarp();

        int cnt = min(32, end - j0);
        if (lane < 24) {
            int k = 0;
            #pragma unroll 4
            for (; k + 1 < cnt; k += 2) {
                int2 pr0 = ps[wib][k];
                int2 pr1 = ps[wib][k + 1];
                float4 h0 = __ldg(h4 + (size_t)pr0.y * 24 + lane);
                float4 h1 = __ldg(h4 + (size_t)pr1.y * 24 + lane);
                unsigned long long p0 = pack_dup(__int_as_float(pr0.x));
                unsigned long long p1 = pack_dup(__int_as_float(pr1.x));
                fma2(accA0, p0, pack_f2(h0.x, h0.y));
                fma2(accA1, p0, pack_f2(h0.z, h0.w));
                fma2(accB0, p1, pack_f2(h1.x, h1.y));
                fma2(accB1, p1, pack_f2(h1.z, h1.w));
            }
            if (k < cnt) {
                int2 pr0 = ps[wib][k];
                float4 h0 = __ldg(h4 + (size_t)pr0.y * 24 + lane);
                unsigned long long p0 = pack_dup(__int_as_float(pr0.x));
                fma2(accA0, p0, pack_f2(h0.x, h0.y));
                fma2(accA1, p0, pack_f2(h0.z, h0.w));
            }
        }
        __syncwarp();
    }
    #pragma unroll
    for (int o = 16; o; o >>= 1) psum += __shfl_xor_sync(0xffffffffu, psum, o);

    float degf = (float)(end - beg);
    float scale = (1.f / fmaxf(psum, 1e-16f)) * (1.f / fmaxf(degf, 1.f));
    if (lane < 24) {
        float2 aA0 = unpack_f2(accA0), aA1 = unpack_f2(accA1);
        float2 aB0 = unpack_f2(accB0), aB1 = unpack_f2(accB1);
        float4 bv = __ldg(reinterpret_cast<const float4*>(bias) + lane);
        float4 r;
        r.x = fmaf(aA0.x + aB0.x, scale, bv.x);
        r.y = fmaf(aA0.y + aB0.y, scale, bv.y);
        r.z = fmaf(aA1.x + aB1.x, scale, bv.z);
        r.w = fmaf(aA1.y + aB1.y, scale, bv.w);
        reinterpret_cast<float4*>(outp)[(size_t)gw * 24 + lane] = r;
    }
}

// ---------------- flat thirds (relu) -> fp16 for gemm2 ----------------
__global__ void k_thirds16(const float* __restrict__ f, int n4) {
    int i = blockIdx.x * blockDim.x + threadIdx.x;
    if (i >= n4) return;
    const float4* f4 = reinterpret_cast<const float4*>(f);
    float4 a = f4[i], b = f4[i + n4], c = f4[i + 2 * n4];
    float4 r;
    r.x = fmaxf(a.x + b.x + c.x, 0.f);
    r.y = fmaxf(a.y + b.y + c.y, 0.f);
    r.z = fmaxf(a.z + b.z + c.z, 0.f);
    r.w = fmaxf(a.w + b.w + c.w, 0.f);
    uint2 u;
    u.x = pack_h2(r.x, r.y);
    u.y = pack_h2(r.z, r.w);
    reinterpret_cast<uint2*>(g_s16)[i] = u;
}

// ---------------- fused flat-thirds -> lin1 -> relu -> lin2 -> sigmoid -------------
__global__ void k_final(const float* __restrict__ t3, const float* __restrict__ Wl1,
                        const float* __restrict__ bl1, const float* __restrict__ Wl2,
                        const float* __restrict__ bl2, float* __restrict__ out, int N) {
    __shared__ float w1s[32 * 96];
    __shared__ float w2s[96 * 32];
    __shared__ float b1s[96];
    __shared__ float b2s[32];
    __shared__ float zs[8][96];
    for (int i = threadIdx.x; i < 3072; i += blockDim.x) {
        w1s[i] = Wl1[i];
        w2s[i] = Wl2[i];
    }
    if (threadIdx.x < 96) b1s[threadIdx.x] = bl1[threadIdx.x];
    if (threadIdx.x < 32) b2s[threadIdx.x] = bl2[threadIdx.x];
    __syncthreads();

    int lane = threadIdx.x & 31;
    int wib = threadIdx.x >> 5;
    int gw = blockIdx.x * 8 + wib;
    int stride = gridDim.x * 8;
    float* zr = zs[wib];
    size_t third = (size_t)N * 32;

    for (int n = gw; n < N; n += stride) {
        size_t idx = (size_t)n * 32 + lane;
        float tv = t3[idx] + t3[third + idx] + t3[2 * third + idx];
        float z0 = b1s[lane], z1 = b1s[lane + 32], z2 = b1s[lane + 64];
        #pragma unroll
        for (int j = 0; j < 32; ++j) {
            float tj = __shfl_sync(0xffffffffu, tv, j);
            z0 = fmaf(tj, w1s[j * 96 + lane], z0);
            z1 = fmaf(tj, w1s[j * 96 + lane + 32], z1);
            z2 = fmaf(tj, w1s[j * 96 + lane + 64], z2);
        }
        zr[lane] = fmaxf(z0, 0.f);
        zr[lane + 32] = fmaxf(z1, 0.f);
        zr[lane + 64] = fmaxf(z2, 0.f);
        __syncwarp();
        float y = b2s[lane];
        #pragma unroll 8
        for (int c = 0; c < 96; ++c) y = fmaf(zr[c], w2s[c * 32 + lane], y);
        out[(size_t)n * 32 + lane] = 1.f / (1.f + __expf(-y));
        __syncwarp();
    }
}

// ---------------- launch ----------------
extern "C" void kernel_launch(void* const* d_in, const int* in_sizes, int n_in,
                              void* d_out, int out_size) {
    const float* x   = (const float*)d_in[0];
    const void*  ei  = d_in[1];
    const float* W1  = (const float*)d_in[2];
    const float* as1 = (const float*)d_in[3];
    const float* ad1 = (const float*)d_in[4];
    const float* b1  = (const float*)d_in[5];
    const float* W2  = (const float*)d_in[6];
    const float* as2 = (const float*)d_in[7];
    const float* ad2 = (const float*)d_in[8];
    const float* b2  = (const float*)d_in[9];
    const float* Wl1 = (const float*)d_in[12];
    const float* bl1 = (const float*)d_in[13];
    const float* Wl2 = (const float*)d_in[14];
    const float* bl2 = (const float*)d_in[15];
    float* out = (float*)d_out;

    int N = in_sizes[0] / 128;
    int E = in_sizes[1] / 2;

    float *p_h, *p_out, *p_es, *p_ed;
    unsigned *p_x16, *p_s16, *p_w16a, *p_w16b;
    cudaGetSymbolAddress((void**)&p_h, g_h);
    cudaGetSymbolAddress((void**)&p_out, g_out);
    cudaGetSymbolAddress((void**)&p_x16, g_x16);
    cudaGetSymbolAddress((void**)&p_s16, g_s16);
    cudaGetSymbolAddress((void**)&p_w16a, g_w16a);
    cudaGetSymbolAddress((void**)&p_w16b, g_w16b);
    cudaGetSymbolAddress((void**)&p_es, g_es);
    cudaGetSymbolAddress((void**)&p_ed, g_ed);

    int warpsBlocks = (N * 32 + 255) / 256;
    int G = (N + 1023) / 1024;

    // 1-4: probe, converts, tensor gemm1+scores (ncu window at #4)
    k_probe<<<1, 32>>>((const int*)ei);
    k_cvt_w<<<30, 256>>>((const float2*)W1, (const float2*)W2);
    k_cvt_x<<<(N * 32 + 255) / 256, 256>>>((const float4*)x, N * 32);
    k_gemm16<128><<<(N + 127) / 128, 256>>>((const __half*)p_x16, (const __half*)p_w16a,
                                            p_h, as1, ad1, p_es, p_ed, N);

    // 5-10: CSR build
    k_init_deg<<<(N + 255) / 256, 256>>>(N);
    k_count<<<(E + 255) / 256, 256>>>(ei, E, N);
    k_scan_blocks<<<G, 1024>>>(N);
    k_scan_sums<<<1, 1024>>>(G, N);
    k_scan_add<<<(N + 255) / 256, 256>>>(N);
    k_fill<<<(E + N + 255) / 256, 256>>>(ei, E, N);

    // layer 1
    k_agg<<<warpsBlocks, 256>>>((const float4*)p_h, b1, p_out, N);
    k_thirds16<<<(N * 8 + 255) / 256, 256>>>(p_out, N * 8);

    // layer 2 (gemm+scores fused)
    k_gemm16<32><<<(N + 127) / 128, 256>>>((const __half*)p_s16, (const __half*)p_w16b,
                                           p_h, as2, ad2, p_es, p_ed, N);
    k_agg<<<warpsBlocks, 256>>>((const float4*)p_h, b2, p_out, N);

    // fused flat-thirds + MLP tail
    k_final<<<1184, 256>>>(p_out, Wl1, bl1, Wl2, bl2, out, N);
}

// round 17
// speedup vs baseline: 1.0570x; 1.0570x over previous
#include <cuda_runtime.h>
#include <cuda_fp16.h>
#include <cstdint>
#include <cstddef>

#define NN 100000
#define EE 1600000
#define TT (EE + NN)

// ---------------- scratch (static device globals; no allocation) ----------------
__device__ unsigned g_h16[(size_t)NN * 48];  // h fp16 (half2-packed, agg payload)
__device__ float    g_out[(size_t)NN * 96];  // agg output (fp32, flat thirds)
__device__ unsigned g_x16[(size_t)NN * 64];  // x fp16 (gemm1 A)
__device__ unsigned g_s16[(size_t)NN * 16];  // thirds out fp16 (gemm2 A)
__device__ unsigned g_w16a[6144];            // W1 fp16
__device__ unsigned g_w16b[1536];            // W2 fp16
__device__ float    g_es[NN];
__device__ float    g_ed[NN];
__device__ int      g_deg[NN];
__device__ int      g_rowptr[NN + 1];
__device__ int      g_cursor[NN];
__device__ int2     g_sd[TT];                // (src, dst) per CSR slot
__device__ int2     g_sp[TT];                // (src, p-bits) per CSR slot
__device__ int      g_bsum[1024];
__device__ int      g_is64;

// ---------------- cp.async / mma helpers ----------------
__device__ __forceinline__ void cp16(void* smem_dst, const void* gsrc, int valid_bytes) {
    unsigned sm = (unsigned)__cvta_generic_to_shared(smem_dst);
    asm volatile("cp.async.cg.shared.global [%0], [%1], 16, %2;"
                 :: "r"(sm), "l"(gsrc), "r"(valid_bytes));
}
__device__ __forceinline__ void cp_commit() {
    asm volatile("cp.async.commit_group;" ::: "memory");
}
__device__ __forceinline__ void cp_wait0() {
    asm volatile("cp.async.wait_group 0;" ::: "memory");
}
__device__ __forceinline__ void ldsm4(unsigned* r, unsigned addr) {
    asm volatile("ldmatrix.sync.aligned.m8n8.x4.shared.b16 {%0,%1,%2,%3}, [%4];"
                 : "=r"(r[0]), "=r"(r[1]), "=r"(r[2]), "=r"(r[3]) : "r"(addr));
}
__device__ __forceinline__ void ldsm4t(unsigned* r, unsigned addr) {
    asm volatile("ldmatrix.sync.aligned.m8n8.x4.trans.shared.b16 {%0,%1,%2,%3}, [%4];"
                 : "=r"(r[0]), "=r"(r[1]), "=r"(r[2]), "=r"(r[3]) : "r"(addr));
}
__device__ __forceinline__ void mma16816(float* d, const unsigned* a, const unsigned* b) {
    asm volatile(
        "mma.sync.aligned.m16n8k16.row.col.f32.f16.f16.f32 "
        "{%0,%1,%2,%3}, {%4,%5,%6,%7}, {%8,%9}, {%0,%1,%2,%3};"
        : "+f"(d[0]), "+f"(d[1]), "+f"(d[2]), "+f"(d[3])
        : "r"(a[0]), "r"(a[1]), "r"(a[2]), "r"(a[3]), "r"(b[0]), "r"(b[1]));
}
__device__ __forceinline__ unsigned pack_h2(float a, float b) {
    __half2 h = __floats2half2_rn(a, b);
    return *reinterpret_cast<unsigned*>(&h);
}

// ---------------- edge-index dtype probe ----------------
__global__ void k_probe(const int* __restrict__ ei32) {
    if (threadIdx.x == 0 && blockIdx.x == 0) {
        int acc = 0;
        #pragma unroll 8
        for (int i = 1; i < 512; i += 2) acc |= ei32[i];
        g_is64 = (acc == 0) ? 1 : 0;
    }
}

__device__ __forceinline__ int load_idx(const void* ei, size_t i, int is64, int N) {
    int v = is64 ? (int)((const long long*)ei)[i] : ((const int*)ei)[i];
    v = v < 0 ? 0 : v;
    return v >= N ? N - 1 : v;
}

// ---------------- fp16 converts ----------------
__global__ void k_cvt_w(const float2* __restrict__ W1, const float2* __restrict__ W2) {
    int i = blockIdx.x * blockDim.x + threadIdx.x;
    if (i < 6144) {
        float2 f = __ldg(W1 + i);
        g_w16a[i] = pack_h2(f.x, f.y);
    } else if (i < 7680) {
        float2 f = __ldg(W2 + (i - 6144));
        g_w16b[i - 6144] = pack_h2(f.x, f.y);
    }
}

__global__ void k_cvt_x(const float4* __restrict__ x4, int n) {
    int i = blockIdx.x * blockDim.x + threadIdx.x;
    if (i >= n) return;
    float4 v = __ldg(x4 + i);
    uint2 u;
    u.x = pack_h2(v.x, v.y);
    u.y = pack_h2(v.z, v.w);
    reinterpret_cast<uint2*>(g_x16)[i] = u;
}

// ---------------- CSR construction ----------------
__global__ void k_init_deg(int N) {
    int i = blockIdx.x * blockDim.x + threadIdx.x;
    if (i < N) g_deg[i] = 1;  // self-loop
}

__global__ void k_count(const void* __restrict__ ei, int E, int N) {
    int i = blockIdx.x * blockDim.x + threadIdx.x;
    if (i < E) {
        int d = load_idx(ei, (size_t)E + i, g_is64, N);
        atomicAdd(&g_deg[d], 1);
    }
}

__global__ void k_scan_blocks(int N) {
    __shared__ int ws[32];
    int i = blockIdx.x * 1024 + threadIdx.x;
    int v = (i < N) ? g_deg[i] : 0;
    int x = v;
    int lane = threadIdx.x & 31, wid = threadIdx.x >> 5;
    #pragma unroll
    for (int o = 1; o < 32; o <<= 1) {
        int y = __shfl_up_sync(0xffffffffu, x, o);
        if (lane >= o) x += y;
    }
    if (lane == 31) ws[wid] = x;
    __syncthreads();
    if (wid == 0) {
        int w = ws[lane];
        #pragma unroll
        for (int o = 1; o < 32; o <<= 1) {
            int y = __shfl_up_sync(0xffffffffu, w, o);
            if (lane >= o) w += y;
        }
        ws[lane] = w;
    }
    __syncthreads();
    int excl = x - v + (wid ? ws[wid - 1] : 0);
    if (i < N) g_rowptr[i] = excl;
    if (threadIdx.x == 1023) g_bsum[blockIdx.x] = ws[31];
}

__global__ void k_scan_sums(int G, int N) {
    __shared__ int ws[32];
    int tid = threadIdx.x;
    int v = (tid < G) ? g_bsum[tid] : 0;
    int x = v;
    int lane = tid & 31, wid = tid >> 5;
    #pragma unroll
    for (int o = 1; o < 32; o <<= 1) {
        int y = __shfl_up_sync(0xffffffffu, x, o);
        if (lane >= o) x += y;
    }
    if (lane == 31) ws[wid] = x;
    __syncthreads();
    if (wid == 0) {
        int w = ws[lane];
        #pragma unroll
        for (int o = 1; o < 32; o <<= 1) {
            int y = __shfl_up_sync(0xffffffffu, w, o);
            if (lane >= o) w += y;
        }
        ws[lane] = w;
    }
    __syncthreads();
    int excl = x - v + (wid ? ws[wid - 1] : 0);
    if (tid < G) g_bsum[tid] = excl;
    if (tid == 1023) g_rowptr[N] = ws[31];
}

__global__ void k_scan_add(int N) {
    int i = blockIdx.x * blockDim.x + threadIdx.x;
    if (i < N) {
        int v = g_rowptr[i] + g_bsum[i >> 10];
        g_rowptr[i] = v;
        g_cursor[i] = v;
    }
}

__global__ void k_fill(const void* __restrict__ ei, int E, int N) {
    int i = blockIdx.x * blockDim.x + threadIdx.x;
    int tot = E + N;
    if (i >= tot) return;
    int s, d;
    if (i < E) {
        int is64 = g_is64;
        s = load_idx(ei, i, is64, N);
        d = load_idx(ei, (size_t)E + i, is64, N);
    } else {
        s = i - E;
        d = s;
    }
    int pos = atomicAdd(&g_cursor[d], 1);
    if (pos < TT) g_sd[pos] = make_int2(s, d);
}

// ---------------- per-edge softmax numerator: p = exp(leaky(es[s]+ed[d])) ----------
// Flat, fully parallel; removes exp + es-gather from the agg critical path.
__global__ void k_edge(int tot) {
    int j = blockIdx.x * blockDim.x + threadIdx.x;
    if (j >= tot) return;
    int2 sd = __ldg(&g_sd[j]);
    float e = __ldg(&g_es[sd.x]) + __ldg(&g_ed[sd.y]);
    e = fmaxf(e, 0.2f * e);
    g_sp[j] = make_int2(sd.x, __float_as_int(__expf(e)));
}

// ---------------- tensor-core GEMM + fused scores (h16 out only) -------------------
template <int K>
__global__ __launch_bounds__(256, 2)
void k_gemm16(const __half* __restrict__ A16, const __half* __restrict__ W16,
              unsigned* __restrict__ h16, const float* __restrict__ a_s,
              const float* __restrict__ a_d, float* __restrict__ es,
              float* __restrict__ ed, int N) {
    constexpr int BK = (K >= 64) ? 64 : K;
    constexpr int NCH = K / BK;
    constexpr int ACH = BK / 8;
    __shared__ __align__(16) __half As[128][BK + 8];
    __shared__ __align__(16) __half Ws[BK][104];
    __shared__ float sdot[128];
    __shared__ float ddot[128];
    int tid = threadIdx.x;
    int lane = tid & 31, wid = tid >> 5;
    int row0 = blockIdx.x * 128;
    int wr = (wid & 3) * 32;
    int wc = (wid >> 2) * 48;

    for (int i = tid; i < 128; i += 256) {
        sdot[i] = 0.f;
        ddot[i] = 0.f;
    }

    float d[2][6][4];
    #pragma unroll
    for (int mi = 0; mi < 2; ++mi)
        #pragma unroll
        for (int nj = 0; nj < 6; ++nj)
            #pragma unroll
            for (int q = 0; q < 4; ++q) d[mi][nj][q] = 0.f;

    for (int ch = 0; ch < NCH; ++ch) {
        for (int i = tid; i < 128 * ACH; i += 256) {
            int r = i / ACH, c = i % ACH;
            bool ok = (row0 + r) < N;
            const __half* src = A16 + (ok ? ((size_t)(row0 + r) * K + ch * BK + c * 8) : 0);
            cp16(&As[r][c * 8], src, ok ? 16 : 0);
        }
        for (int i = tid; i < BK * 12; i += 256) {
            int k = i / 12, c = i % 12;
            cp16(&Ws[k][c * 8], W16 + (size_t)(ch * BK + k) * 96 + c * 8, 16);
        }
        cp_commit();
        cp_wait0();
        __syncthreads();

        #pragma unroll
        for (int k0 = 0; k0 < BK; k0 += 16) {
            unsigned a[2][4], b[3][4];
            #pragma unroll
            for (int mi = 0; mi < 2; ++mi)
                ldsm4(a[mi], (unsigned)__cvta_generic_to_shared(
                                 &As[wr + mi * 16 + (lane & 15)][k0 + (lane >> 4) * 8]));
            #pragma unroll
            for (int nj = 0; nj < 3; ++nj)
                ldsm4t(b[nj], (unsigned)__cvta_generic_to_shared(
                                  &Ws[k0 + (lane & 15)][wc + nj * 16 + (lane >> 4) * 8]));
            #pragma unroll
            for (int mi = 0; mi < 2; ++mi)
                #pragma unroll
                for (int nj = 0; nj < 6; ++nj)
                    mma16816(d[mi][nj], a[mi], &b[nj >> 1][(nj & 1) * 2]);
        }
        __syncthreads();
    }

    int groupID = lane >> 2;
    int c0 = (lane & 3) * 2;
    float sa[2][2] = {{0.f, 0.f}, {0.f, 0.f}};
    float da[2][2] = {{0.f, 0.f}, {0.f, 0.f}};
    #pragma unroll
    for (int mi = 0; mi < 2; ++mi) {
        int r1 = row0 + wr + mi * 16 + groupID;
        int r2 = r1 + 8;
        #pragma unroll
        for (int nj = 0; nj < 6; ++nj) {
            int col = wc + nj * 8 + c0;
            float as0 = __ldg(&a_s[col]), as1 = __ldg(&a_s[col + 1]);
            float ad0 = __ldg(&a_d[col]), ad1 = __ldg(&a_d[col + 1]);
            sa[mi][0] += d[mi][nj][0] * as0 + d[mi][nj][1] * as1;
            da[mi][0] += d[mi][nj][0] * ad0 + d[mi][nj][1] * ad1;
            sa[mi][1] += d[mi][nj][2] * as0 + d[mi][nj][3] * as1;
            da[mi][1] += d[mi][nj][2] * ad0 + d[mi][nj][3] * ad1;
            if (r1 < N) h16[(size_t)r1 * 48 + col / 2] = pack_h2(d[mi][nj][0], d[mi][nj][1]);
            if (r2 < N) h16[(size_t)r2 * 48 + col / 2] = pack_h2(d[mi][nj][2], d[mi][nj][3]);
        }
        int lr1 = wr + mi * 16 + groupID;
        atomicAdd(&sdot[lr1], sa[mi][0]);
        atomicAdd(&ddot[lr1], da[mi][0]);
        atomicAdd(&sdot[lr1 + 8], sa[mi][1]);
        atomicAdd(&ddot[lr1 + 8], da[mi][1]);
    }
    __syncthreads();
    for (int i = tid; i < 128; i += 256) {
        int r = row0 + i;
        if (r < N) {
            es[r] = sdot[i];
            ed[r] = ddot[i];
        }
    }
}

// ---------------- warp-per-node aggregation over precomputed (s,p) pairs -----------
// Two 12-lane groups process 2 edges/step; only chain is sp->h (unroll 4 => 4 in flight).
// No exp / no shfl / no syncwarp in the loop. psum via cg==0 lanes + 1 shuffle.
__global__ void k_agg(const uint4* __restrict__ h16, const int2* __restrict__ sp,
                      const float* __restrict__ bias, float* __restrict__ outp, int N) {
    int gw = (blockIdx.x * blockDim.x + threadIdx.x) >> 5;
    if (gw >= N) return;
    int lane = threadIdx.x & 31;
    int beg = g_rowptr[gw], end = g_rowptr[gw + 1];
    int grp = (lane >= 12) ? 1 : 0;
    int cg = lane % 12;

    float a0 = 0.f, a1 = 0.f, a2 = 0.f, a3 = 0.f;
    float a4 = 0.f, a5 = 0.f, a6 = 0.f, a7 = 0.f;
    float psum = 0.f;

    if (lane < 24) {
        #pragma unroll 4
        for (int j = beg + grp; j < end; j += 2) {
            int2 v = __ldg(sp + j);
            float p = __int_as_float(v.y);
            uint4 hv = __ldg(h16 + (size_t)v.x * 12 + cg);
            const __half2* hh = reinterpret_cast<const __half2*>(&hv);
            float2 f0 = __half22float2(hh[0]);
            float2 f1 = __half22float2(hh[1]);
            float2 f2 = __half22float2(hh[2]);
            float2 f3 = __half22float2(hh[3]);
            a0 = fmaf(p, f0.x, a0);
            a1 = fmaf(p, f0.y, a1);
            a2 = fmaf(p, f1.x, a2);
            a3 = fmaf(p, f1.y, a3);
            a4 = fmaf(p, f2.x, a4);
            a5 = fmaf(p, f2.y, a5);
            a6 = fmaf(p, f3.x, a6);
            a7 = fmaf(p, f3.y, a7);
            if (cg == 0) psum += p;
        }
    }

    // combine the two groups: lane l (<12) += lane l+12
    float r0 = a0 + __shfl_sync(0xffffffffu, a0, lane + 12);
    float r1 = a1 + __shfl_sync(0xffffffffu, a1, lane + 12);
    float r2 = a2 + __shfl_sync(0xffffffffu, a2, lane + 12);
    float r3 = a3 + __shfl_sync(0xffffffffu, a3, lane + 12);
    float r4 = a4 + __shfl_sync(0xffffffffu, a4, lane + 12);
    float r5 = a5 + __shfl_sync(0xffffffffu, a5, lane + 12);
    float r6 = a6 + __shfl_sync(0xffffffffu, a6, lane + 12);
    float r7 = a7 + __shfl_sync(0xffffffffu, a7, lane + 12);
    float ps = __shfl_sync(0xffffffffu, psum, 0) + __shfl_sync(0xffffffffu, psum, 12);

    float degf = (float)(end - beg);
    float scale = (1.f / fmaxf(ps, 1e-16f)) * (1.f / fmaxf(degf, 1.f));
    if (lane < 12) {
        const float4* b4 = reinterpret_cast<const float4*>(bias);
        float4 bv0 = __ldg(b4 + lane * 2);
        float4 bv1 = __ldg(b4 + lane * 2 + 1);
        float4 o0, o1;
        o0.x = fmaf(r0, scale, bv0.x);
        o0.y = fmaf(r1, scale, bv0.y);
        o0.z = fmaf(r2, scale, bv0.z);
        o0.w = fmaf(r3, scale, bv0.w);
        o1.x = fmaf(r4, scale, bv1.x);
        o1.y = fmaf(r5, scale, bv1.y);
        o1.z = fmaf(r6, scale, bv1.z);
        o1.w = fmaf(r7, scale, bv1.w);
        float4* op = reinterpret_cast<float4*>(outp) + (size_t)gw * 24 + lane * 2;
        op[0] = o0;
        op[1] = o1;
    }
}

// ---------------- flat thirds (relu) -> fp16 for gemm2 ----------------
__global__ void k_thirds16(const float* __restrict__ f, int n4) {
    int i = blockIdx.x * blockDim.x + threadIdx.x;
    if (i >= n4) return;
    const float4* f4 = reinterpret_cast<const float4*>(f);
    float4 a = f4[i], b = f4[i + n4], c = f4[i + 2 * n4];
    float4 r;
    r.x = fmaxf(a.x + b.x + c.x, 0.f);
    r.y = fmaxf(a.y + b.y + c.y, 0.f);
    r.z = fmaxf(a.z + b.z + c.z, 0.f);
    r.w = fmaxf(a.w + b.w + c.w, 0.f);
    uint2 u;
    u.x = pack_h2(r.x, r.y);
    u.y = pack_h2(r.z, r.w);
    reinterpret_cast<uint2*>(g_s16)[i] = u;
}

// ---------------- fused flat-thirds -> lin1 -> relu -> lin2 -> sigmoid -------------
__global__ void k_final(const float* __restrict__ t3, const float* __restrict__ Wl1,
                        const float* __restrict__ bl1, const float* __restrict__ Wl2,
                        const float* __restrict__ bl2, float* __restrict__ out, int N) {
    __shared__ float w1s[32 * 96];
    __shared__ float w2s[96 * 32];
    __shared__ float b1s[96];
    __shared__ float b2s[32];
    __shared__ float zs[8][96];
    for (int i = threadIdx.x; i < 3072; i += blockDim.x) {
        w1s[i] = Wl1[i];
        w2s[i] = Wl2[i];
    }
    if (threadIdx.x < 96) b1s[threadIdx.x] = bl1[threadIdx.x];
    if (threadIdx.x < 32) b2s[threadIdx.x] = bl2[threadIdx.x];
    __syncthreads();

    int lane = threadIdx.x & 31;
    int wib = threadIdx.x >> 5;
    int gw = blockIdx.x * 8 + wib;
    int stride = gridDim.x * 8;
    float* zr = zs[wib];
    size_t third = (size_t)N * 32;

    for (int n = gw; n < N; n += stride) {
        size_t idx = (size_t)n * 32 + lane;
        float tv = t3[idx] + t3[third + idx] + t3[2 * third + idx];
        float z0 = b1s[lane], z1 = b1s[lane + 32], z2 = b1s[lane + 64];
        #pragma unroll
        for (int j = 0; j < 32; ++j) {
            float tj = __shfl_sync(0xffffffffu, tv, j);
            z0 = fmaf(tj, w1s[j * 96 + lane], z0);
            z1 = fmaf(tj, w1s[j * 96 + lane + 32], z1);
            z2 = fmaf(tj, w1s[j * 96 + lane + 64], z2);
        }
        zr[lane] = fmaxf(z0, 0.f);
        zr[lane + 32] = fmaxf(z1, 0.f);
        zr[lane + 64] = fmaxf(z2, 0.f);
        __syncwarp();
        float y = b2s[lane];
        #pragma unroll 8
        for (int c = 0; c < 96; ++c) y = fmaf(zr[c], w2s[c * 32 + lane], y);
        out[(size_t)n * 32 + lane] = 1.f / (1.f + __expf(-y));
        __syncwarp();
    }
}

// ---------------- launch ----------------
extern "C" void kernel_launch(void* const* d_in, const int* in_sizes, int n_in,
                              void* d_out, int out_size) {
    const float* x   = (const float*)d_in[0];
    const void*  ei  = d_in[1];
    const float* W1  = (const float*)d_in[2];
    const float* as1 = (const float*)d_in[3];
    const float* ad1 = (const float*)d_in[4];
    const float* b1  = (const float*)d_in[5];
    const float* W2  = (const float*)d_in[6];
    const float* as2 = (const float*)d_in[7];
    const float* ad2 = (const float*)d_in[8];
    const float* b2  = (const float*)d_in[9];
    const float* Wl1 = (const float*)d_in[12];
    const float* bl1 = (const float*)d_in[13];
    const float* Wl2 = (const float*)d_in[14];
    const float* bl2 = (const float*)d_in[15];
    float* out = (float*)d_out;

    int N = in_sizes[0] / 128;
    int E = in_sizes[1] / 2;
    int tot = E + N;

    float *p_out, *p_es, *p_ed;
    unsigned *p_h16, *p_x16, *p_s16, *p_w16a, *p_w16b;
    int2* p_sp;
    cudaGetSymbolAddress((void**)&p_h16, g_h16);
    cudaGetSymbolAddress((void**)&p_out, g_out);
    cudaGetSymbolAddress((void**)&p_x16, g_x16);
    cudaGetSymbolAddress((void**)&p_s16, g_s16);
    cudaGetSymbolAddress((void**)&p_w16a, g_w16a);
    cudaGetSymbolAddress((void**)&p_w16b, g_w16b);
    cudaGetSymbolAddress((void**)&p_es, g_es);
    cudaGetSymbolAddress((void**)&p_ed, g_ed);
    cudaGetSymbolAddress((void**)&p_sp, g_sp);

    int warpsBlocks = (N * 32 + 255) / 256;
    int G = (N + 1023) / 1024;

    // 1-4: probe, converts, tensor gemm1+scores (ncu window at #4)
    k_probe<<<1, 32>>>((const int*)ei);
    k_cvt_w<<<30, 256>>>((const float2*)W1, (const float2*)W2);
    k_cvt_x<<<(N * 32 + 255) / 256, 256>>>((const float4*)x, N * 32);
    k_gemm16<128><<<(N + 127) / 128, 256>>>((const __half*)p_x16, (const __half*)p_w16a,
                                            p_h16, as1, ad1, p_es, p_ed, N);

    // 5-10: CSR build (stores (src,dst) pairs)
    k_init_deg<<<(N + 255) / 256, 256>>>(N);
    k_count<<<(E + 255) / 256, 256>>>(ei, E, N);
    k_scan_blocks<<<G, 1024>>>(N);
    k_scan_sums<<<1, 1024>>>(G, N);
    k_scan_add<<<(N + 255) / 256, 256>>>(N);
    k_fill<<<(E + N + 255) / 256, 256>>>(ei, E, N);

    // layer 1: edge-p precompute, then gather-agg
    k_edge<<<(tot + 255) / 256, 256>>>(tot);
    k_agg<<<warpsBlocks, 256>>>((const uint4*)p_h16, p_sp, b1, p_out, N);
    k_thirds16<<<(N * 8 + 255) / 256, 256>>>(p_out, N * 8);

    // layer 2 (gemm+scores fused)
    k_gemm16<32><<<(N + 127) / 128, 256>>>((const __half*)p_s16, (const __half*)p_w16b,
                                           p_h16, as2, ad2, p_es, p_ed, N);
    k_edge<<<(tot + 255) / 256, 256>>>(tot);
    k_agg<<<warpsBlocks, 256>>>((const uint4*)p_h16, p_sp, b2, p_out, N);

    // fused flat-thirds + MLP tail
    k_final<<<1184, 256>>>(p_out, Wl1, bl1, Wl2, bl2, out, N);
}